// round 7
// baseline (speedup 1.0000x reference)
#include <cuda_runtime.h>
#include <cuda_fp16.h>
#include <cstdint>
#include <math.h>

static constexpr int B_ = 8, S_ = 2048, D_ = 1024, H_ = 1024;
static constexpr int M_ = B_ * S_;  // 16384

// Tiling: 128x128 CTA tile, BK=32. fp16 planes in SMEM: A_h, B_h, B_l.
static constexpr int BM = 128, BN = 128, BK = 32;
static constexpr int ROWB = 80;                    // 64 data bytes + 16 pad
static constexpr int PL = BM * ROWB;               // 10240 per plane
static constexpr int STG = 3 * PL;                 // 30720 per stage
static constexpr int NST = 3;
static constexpr int SMEM_BYTES = NST * STG;       // 92160

// Device scratch (allocation-free rule: __device__ globals)
__device__ __half g_xh[(size_t)M_ * D_];
__device__ __half g_wh[3][(size_t)H_ * D_];
__device__ __half g_wl[3][(size_t)H_ * D_];
__device__ __half g_qh[(size_t)M_ * H_];
__device__ __half g_kh[(size_t)M_ * H_];
__device__ __half g_kl[(size_t)M_ * H_];
__device__ __half g_vh[(size_t)M_ * H_];
__device__ __half g_vl[(size_t)M_ * H_];
__device__ __half g_vth[(size_t)M_ * H_];
__device__ __half g_vtl[(size_t)M_ * H_];
__device__ float  g_p [(size_t)B_ * S_ * S_];
__device__ __half g_ph[(size_t)B_ * S_ * S_];

// ---------------------------------------------------------------------------
// helpers
// ---------------------------------------------------------------------------
__device__ __forceinline__ uint32_t smem_u32(const void* p) {
    uint32_t a;
    asm("{ .reg .u64 t; cvta.to.shared.u64 t, %1; cvt.u32.u64 %0, t; }"
        : "=r"(a) : "l"(p));
    return a;
}

#define CP16(dst, src) \
    asm volatile("cp.async.cg.shared.global [%0], [%1], 16;" :: "r"(dst), "l"(src))
#define CP_COMMIT() asm volatile("cp.async.commit_group;" ::: "memory")
#define CP_WAIT1()  asm volatile("cp.async.wait_group 1;" ::: "memory")

__device__ __forceinline__ void mma16(float* d, const uint32_t* a, const uint32_t* b) {
    asm volatile(
        "mma.sync.aligned.m16n8k16.row.col.f32.f16.f16.f32 "
        "{%0,%1,%2,%3},{%4,%5,%6,%7},{%8,%9},{%0,%1,%2,%3};"
        : "+f"(d[0]), "+f"(d[1]), "+f"(d[2]), "+f"(d[3])
        : "r"(a[0]), "r"(a[1]), "r"(a[2]), "r"(a[3]), "r"(b[0]), "r"(b[1]));
}

__device__ __forceinline__ void ldsm4(uint32_t* r, uint32_t addr) {
    asm volatile(
        "ldmatrix.sync.aligned.m8n8.x4.shared.b16 {%0,%1,%2,%3}, [%4];"
        : "=r"(r[0]), "=r"(r[1]), "=r"(r[2]), "=r"(r[3]) : "r"(addr));
}

// ---------------------------------------------------------------------------
// Per-stage compute: 2 k16 steps, warp tile 64x32, fp16x2 via ldmatrix.
// Hi and lo MMA passes are separated so no accumulator sees back-to-back
// dependent HMMAs (RAW distance = 16 MMAs, covering HMMA latency).
// ---------------------------------------------------------------------------
__device__ __forceinline__ void compute_tile(
    uint32_t buf, float (&acc)[4][4][4], uint32_t aBase, uint32_t bBase)
{
#pragma unroll
    for (int ks = 0; ks < 2; ks++) {
        const uint32_t kb = ks * 32;
        uint32_t bh[2][4], bl[2][4];
#pragma unroll
        for (int ntp = 0; ntp < 2; ntp++) {
            const uint32_t ba = buf + PL + bBase + ntp * 16 * ROWB + kb;
            ldsm4(bh[ntp], ba);
            ldsm4(bl[ntp], ba + PL);
        }
        // hi pass: 16 independent accumulators
#pragma unroll
        for (int mt = 0; mt < 4; mt++) {
            uint32_t af[4];
            ldsm4(af, buf + aBase + mt * 16 * ROWB + kb);
#pragma unroll
            for (int nt = 0; nt < 4; nt++) {
                const int ntp = nt >> 1, s = nt & 1;
                uint32_t b0[2] = {bh[ntp][s], bh[ntp][s + 2]};
                mma16(acc[mt][nt], af, b0);  // a_hi * b_hi
            }
        }
        // lo pass
#pragma unroll
        for (int mt = 0; mt < 4; mt++) {
            uint32_t af[4];
            ldsm4(af, buf + aBase + mt * 16 * ROWB + kb);
#pragma unroll
            for (int nt = 0; nt < 4; nt++) {
                const int ntp = nt >> 1, s = nt & 1;
                uint32_t b1[2] = {bl[ntp][s], bl[ntp][s + 2]};
                mma16(acc[mt][nt], af, b1);  // a_hi * b_lo
            }
        }
    }
}

// ---------------------------------------------------------------------------
// NT GEMM on pre-split fp16 planes: C[m,n] = sum_k A[m,k]*B[n,k]
// MODE 0: Q epilogue   -> half plane + bias
// MODE 1: KV epilogue  -> half hi+lo planes + bias
// MODE 2: scores       -> fp32, scale + causal mask (skip masked tiles)
// MODE 3: PV/out       -> fp32 plain, Kend = m0+BM
// ---------------------------------------------------------------------------
template <int MODE>
__global__ __launch_bounds__(256, 2) void gemm_h(
    const __half* __restrict__ A, const __half* __restrict__ Bh,
    const __half* __restrict__ Bl, const float* __restrict__ bias,
    void* __restrict__ C0, void* __restrict__ C1,
    int K, int lda, int ldb, int ldc,
    long sAz, long sBz, long sCz, float scale)
{
    const int m0 = blockIdx.y * BM;
    const int n0 = blockIdx.x * BN;
    if (MODE == 2 && n0 > m0) return;  // fully masked tile

    const int z = blockIdx.z;
    A  += (size_t)z * sAz;
    Bh += (size_t)z * sBz;
    Bl += (size_t)z * sBz;

    extern __shared__ char smx[];
    const uint32_t smb = smem_u32(smx);

    const int tid  = threadIdx.x;
    const int lane = tid & 31;
    const int wid  = tid >> 5;
    const int wm   = wid >> 2;   // 0..1 (64 rows)
    const int wn   = wid & 3;    // 0..3 (32 cols)
    const int g    = lane >> 2;
    const int tg   = lane & 3;

    // ldmatrix lane addressing
    const uint32_t lq = lane & 15, lh = lane >> 4;
    const uint32_t aBase = (wm * 64 + lq) * ROWB + lh * 16;
    const uint32_t bBase = (wn * 32 + lq) * ROWB + lh * 16;

    const int Kend = (MODE == 3) ? (m0 + BM) : K;
    const int KT   = Kend / BK;

    // cp.async mapping: rows lr4 and lr4+64, 16B segment c of the 64B row
    const int lr4 = tid >> 2;
    const int c16 = tid & 3;
    const __half* pA  = A  + (size_t)(m0 + lr4) * lda + c16 * 8;
    const __half* pBh = Bh + (size_t)(n0 + lr4) * ldb + c16 * 8;
    const __half* pBl = Bl + (size_t)(n0 + lr4) * ldb + c16 * 8;
    const size_t a64 = (size_t)64 * lda, b64 = (size_t)64 * ldb;
    const uint32_t dst0 = smb + lr4 * ROWB + c16 * 16;

    float acc[4][4][4];
#pragma unroll
    for (int i = 0; i < 4; i++)
#pragma unroll
        for (int j = 0; j < 4; j++)
#pragma unroll
            for (int e = 0; e < 4; e++) acc[i][j][e] = 0.f;

#define ISSUE(kt)                                                          \
    do {                                                                   \
        const uint32_t d = dst0 + ((kt) % NST) * STG;                      \
        const int koff = (kt) * BK;                                        \
        CP16(d,                  pA  + koff);                              \
        CP16(d + 64 * ROWB,      pA  + koff + a64);                        \
        CP16(d + PL,             pBh + koff);                              \
        CP16(d + PL + 64 * ROWB, pBh + koff + b64);                        \
        CP16(d + 2 * PL,             pBl + koff);                          \
        CP16(d + 2 * PL + 64 * ROWB, pBl + koff + b64);                    \
        CP_COMMIT();                                                       \
    } while (0)

    ISSUE(0);
    ISSUE(1);

    for (int kt = 0; kt < KT; kt++) {
        CP_WAIT1();          // stage kt resident
        __syncthreads();     // all warps done with buffer being rewritten
        if (kt + 2 < KT) ISSUE(kt + 2);
        compute_tile(smb + (kt % NST) * STG, acc, aBase, bBase);
    }
#undef ISSUE

    // epilogue
#pragma unroll
    for (int mt = 0; mt < 4; mt++)
#pragma unroll
        for (int nt = 0; nt < 4; nt++) {
            const int row = m0 + wm * 64 + mt * 16 + g;
            const int col = n0 + wn * 32 + nt * 8 + tg * 2;
            float* c = acc[mt][nt];
            if (MODE == 0) {
                __half* Ch = (__half*)C0;
                const float2 b2 = *(const float2*)(bias + col);
                __half2 h0 = __floats2half2_rn(c[0] + b2.x, c[1] + b2.y);
                __half2 h1 = __floats2half2_rn(c[2] + b2.x, c[3] + b2.y);
                *(__half2*)(Ch + (size_t)row * ldc + col)       = h0;
                *(__half2*)(Ch + (size_t)(row + 8) * ldc + col) = h1;
            } else if (MODE == 1) {
                __half* Ch = (__half*)C0;
                __half* Cl = (__half*)C1;
                const float2 b2 = *(const float2*)(bias + col);
                const float v0 = c[0] + b2.x, v1 = c[1] + b2.y;
                const float v2 = c[2] + b2.x, v3 = c[3] + b2.y;
                __half2 h0 = __floats2half2_rn(v0, v1);
                __half2 h1 = __floats2half2_rn(v2, v3);
                __half2 l0 = __floats2half2_rn(v0 - __half2float(__low2half(h0)),
                                               v1 - __half2float(__high2half(h0)));
                __half2 l1 = __floats2half2_rn(v2 - __half2float(__low2half(h1)),
                                               v3 - __half2float(__high2half(h1)));
                *(__half2*)(Ch + (size_t)row * ldc + col)       = h0;
                *(__half2*)(Ch + (size_t)(row + 8) * ldc + col) = h1;
                *(__half2*)(Cl + (size_t)row * ldc + col)       = l0;
                *(__half2*)(Cl + (size_t)(row + 8) * ldc + col) = l1;
            } else if (MODE == 2) {
                float* C = (float*)C0 + (size_t)z * sCz;
                float2 v0, v1;
                v0.x = (col     <= row    ) ? c[0] * scale : -1e9f;
                v0.y = (col + 1 <= row    ) ? c[1] * scale : -1e9f;
                v1.x = (col     <= row + 8) ? c[2] * scale : -1e9f;
                v1.y = (col + 1 <= row + 8) ? c[3] * scale : -1e9f;
                *(float2*)(C + (size_t)row * ldc + col)       = v0;
                *(float2*)(C + (size_t)(row + 8) * ldc + col) = v1;
            } else {
                float* C = (float*)C0 + (size_t)z * sCz;
                *(float2*)(C + (size_t)row * ldc + col)       = make_float2(c[0], c[1]);
                *(float2*)(C + (size_t)(row + 8) * ldc + col) = make_float2(c[2], c[3]);
            }
        }
}

// ---------------------------------------------------------------------------
// Conversion kernels (fp32 -> fp16 planes)
// ---------------------------------------------------------------------------
__global__ __launch_bounds__(256) void cvt_h(
    const float* __restrict__ in, __half* __restrict__ out)
{
    const size_t i = ((size_t)blockIdx.x * 256 + threadIdx.x) * 4;
    float4 v = *(const float4*)(in + i);
    __half2 a = __floats2half2_rn(v.x, v.y);
    __half2 b = __floats2half2_rn(v.z, v.w);
    *(__half2*)(out + i)     = a;
    *(__half2*)(out + i + 2) = b;
}

__global__ __launch_bounds__(256) void cvt_hl(
    const float* __restrict__ in, __half* __restrict__ oh, __half* __restrict__ ol)
{
    const size_t i = ((size_t)blockIdx.x * 256 + threadIdx.x) * 4;
    float4 v = *(const float4*)(in + i);
    __half2 h0 = __floats2half2_rn(v.x, v.y);
    __half2 h1 = __floats2half2_rn(v.z, v.w);
    __half2 l0 = __floats2half2_rn(v.x - __half2float(__low2half(h0)),
                                   v.y - __half2float(__high2half(h0)));
    __half2 l1 = __floats2half2_rn(v.z - __half2float(__low2half(h1)),
                                   v.w - __half2float(__high2half(h1)));
    *(__half2*)(oh + i)     = h0;
    *(__half2*)(oh + i + 2) = h1;
    *(__half2*)(ol + i)     = l0;
    *(__half2*)(ol + i + 2) = l1;
}

// ---------------------------------------------------------------------------
// fp16 transpose: in [M_][H_] -> out [H_][M_]
// ---------------------------------------------------------------------------
__global__ __launch_bounds__(256) void transpose_h(
    const __half* __restrict__ in, __half* __restrict__ out)
{
    __shared__ __half t[32][34];
    const int x0 = blockIdx.x * 32;
    const int y0 = blockIdx.y * 32;
    const int tx = threadIdx.x & 31;
    const int ty = threadIdx.x >> 5;
#pragma unroll
    for (int j = 0; j < 32; j += 8)
        t[ty + j][tx] = in[(size_t)(y0 + ty + j) * H_ + x0 + tx];
    __syncthreads();
#pragma unroll
    for (int j = 0; j < 32; j += 8)
        out[(size_t)(x0 + ty + j) * M_ + y0 + tx] = t[tx][ty + j];
}

// ---------------------------------------------------------------------------
// Row softmax: read fp32 scores, write fp16 probabilities (causal prefix).
// ---------------------------------------------------------------------------
__global__ __launch_bounds__(256) void softmax_rows(
    const float* __restrict__ P, __half* __restrict__ Ph)
{
    const int r = blockIdx.x;
    const int m = r & (S_ - 1);
    const float* row = P + (size_t)r * S_;
    __half* orow = Ph + (size_t)r * S_;
    const int KB = ((m >> 7) + 1) << 7;

    __shared__ float buf[S_];
    __shared__ float red[8];
    const int tid = threadIdx.x;

    float mx = -3.4e38f;
    for (int i = tid; i < KB; i += 256) {
        float v = row[i];
        buf[i] = v;
        mx = fmaxf(mx, v);
    }
#pragma unroll
    for (int o = 16; o; o >>= 1) mx = fmaxf(mx, __shfl_xor_sync(0xffffffffu, mx, o));
    if ((tid & 31) == 0) red[tid >> 5] = mx;
    __syncthreads();
    if (tid == 0) {
        float t = red[0];
#pragma unroll
        for (int i = 1; i < 8; i++) t = fmaxf(t, red[i]);
        red[0] = t;
    }
    __syncthreads();
    mx = red[0];
    __syncthreads();

    float sm = 0.f;
    for (int i = tid; i < KB; i += 256) {
        float e = expf(buf[i] - mx);
        buf[i] = e;
        sm += e;
    }
#pragma unroll
    for (int o = 16; o; o >>= 1) sm += __shfl_xor_sync(0xffffffffu, sm, o);
    __syncthreads();
    if ((tid & 31) == 0) red[tid >> 5] = sm;
    __syncthreads();
    if (tid == 0) {
        float t = 0.f;
#pragma unroll
        for (int i = 0; i < 8; i++) t += red[i];
        red[0] = t;
    }
    __syncthreads();
    const float inv = 1.f / red[0];

    for (int i = tid; i < KB; i += 256)
        orow[i] = __float2half_rn(buf[i] * inv);
}

// ---------------------------------------------------------------------------
// Launch pipeline (graph-capturable)
// ---------------------------------------------------------------------------
extern "C" void kernel_launch(void* const* d_in, const int* in_sizes, int n_in,
                              void* d_out, int out_size)
{
    (void)in_sizes; (void)n_in; (void)out_size;
    const float* x  = (const float*)d_in[0];
    const float* Wq = (const float*)d_in[1];
    const float* bq = (const float*)d_in[2];
    const float* Wk = (const float*)d_in[3];
    const float* bk = (const float*)d_in[4];
    const float* Wv = (const float*)d_in[5];
    const float* bv = (const float*)d_in[6];
    float* out = (float*)d_out;

    __half *xh, *qh, *kh, *kl, *vh, *vl, *vth, *vtl, *ph;
    __half (*wh)[(size_t)H_ * D_];
    __half (*wl)[(size_t)H_ * D_];
    float* p;
    cudaGetSymbolAddress((void**)&xh,  g_xh);
    cudaGetSymbolAddress((void**)&wh,  g_wh);
    cudaGetSymbolAddress((void**)&wl,  g_wl);
    cudaGetSymbolAddress((void**)&qh,  g_qh);
    cudaGetSymbolAddress((void**)&kh,  g_kh);
    cudaGetSymbolAddress((void**)&kl,  g_kl);
    cudaGetSymbolAddress((void**)&vh,  g_vh);
    cudaGetSymbolAddress((void**)&vl,  g_vl);
    cudaGetSymbolAddress((void**)&vth, g_vth);
    cudaGetSymbolAddress((void**)&vtl, g_vtl);
    cudaGetSymbolAddress((void**)&p,   g_p);
    cudaGetSymbolAddress((void**)&ph,  g_ph);

    cudaFuncSetAttribute(gemm_h<0>, cudaFuncAttributeMaxDynamicSharedMemorySize, SMEM_BYTES);
    cudaFuncSetAttribute(gemm_h<1>, cudaFuncAttributeMaxDynamicSharedMemorySize, SMEM_BYTES);
    cudaFuncSetAttribute(gemm_h<2>, cudaFuncAttributeMaxDynamicSharedMemorySize, SMEM_BYTES);
    cudaFuncSetAttribute(gemm_h<3>, cudaFuncAttributeMaxDynamicSharedMemorySize, SMEM_BYTES);

    const dim3 blk(256);

    // 0) pre-split operands to fp16 planes
    cvt_h <<<M_ * D_ / 1024, blk>>>(x, xh);
    cvt_hl<<<H_ * D_ / 1024, blk>>>(Wq, wh[0], wl[0]);
    cvt_hl<<<H_ * D_ / 1024, blk>>>(Wk, wh[1], wl[1]);
    cvt_hl<<<H_ * D_ / 1024, blk>>>(Wv, wh[2], wl[2]);

    // 1) QKV projections (A = xh; B = W hi/lo)
    const dim3 gq(H_ / BN, M_ / BM, 1);
    gemm_h<0><<<gq, blk, SMEM_BYTES>>>(xh, wh[0], wl[0], bq, qh, nullptr,
                                       D_, D_, D_, H_, 0, 0, 0, 1.f);
    gemm_h<1><<<gq, blk, SMEM_BYTES>>>(xh, wh[1], wl[1], bk, kh, kl,
                                       D_, D_, D_, H_, 0, 0, 0, 1.f);
    gemm_h<1><<<gq, blk, SMEM_BYTES>>>(xh, wh[2], wl[2], bv, vh, vl,
                                       D_, D_, D_, H_, 0, 0, 0, 1.f);

    // 1b) V^T planes for the PV GEMM
    const dim3 gt(H_ / 32, M_ / 32);
    transpose_h<<<gt, blk>>>(vh, vth);
    transpose_h<<<gt, blk>>>(vl, vtl);

    // 2) Scores: per batch, Q @ K^T / 32, causal
    const dim3 gs(S_ / BN, S_ / BM, B_);
    gemm_h<2><<<gs, blk, SMEM_BYTES>>>(qh, kh, kl, nullptr, p, nullptr,
                                       H_, H_, H_, S_,
                                       (long)S_ * H_, (long)S_ * H_, (long)S_ * S_,
                                       0.03125f);

    // 3) Row softmax -> fp16 P
    softmax_rows<<<M_, blk>>>(p, ph);

    // 4) O = P @ V (B = V^T hi/lo planes, causal k-limit)
    const dim3 gp(H_ / BN, S_ / BM, B_);
    gemm_h<3><<<gp, blk, SMEM_BYTES>>>(ph, vth, vtl, nullptr, out, nullptr,
                                       S_, S_, M_, H_,
                                       (long)S_ * S_, (long)S_, (long)S_ * H_, 1.f);
}

// round 8
// speedup vs baseline: 1.7612x; 1.7612x over previous
#include <cuda_runtime.h>
#include <cuda_fp16.h>
#include <cstdint>
#include <math.h>

static constexpr int B_ = 8, S_ = 2048, D_ = 1024, H_ = 1024;
static constexpr int M_ = B_ * S_;  // 16384

// Tiling: 128x128 CTA tile, BK=32. fp16 planes in SMEM: A_h, B_h.
static constexpr int BM = 128, BN = 128, BK = 32;
static constexpr int ROWB = 80;                    // 64 data bytes + 16 pad
static constexpr int PL = BM * ROWB;               // 10240 per plane
static constexpr int STG = 2 * PL;                 // 20480 per stage
static constexpr int NST = 4;
static constexpr int SMEM_BYTES = NST * STG;       // 81920

// Device scratch (allocation-free rule: __device__ globals)
__device__ __half g_xh[(size_t)M_ * D_];
__device__ __half g_wh[3][(size_t)H_ * D_];
__device__ __half g_qh[(size_t)M_ * H_];
__device__ __half g_kh[(size_t)M_ * H_];
__device__ __half g_vh[(size_t)M_ * H_];
__device__ __half g_vth[(size_t)M_ * H_];
__device__ float  g_p [(size_t)B_ * S_ * S_];
__device__ __half g_ph[(size_t)B_ * S_ * S_];

// ---------------------------------------------------------------------------
// helpers
// ---------------------------------------------------------------------------
__device__ __forceinline__ uint32_t smem_u32(const void* p) {
    uint32_t a;
    asm("{ .reg .u64 t; cvta.to.shared.u64 t, %1; cvt.u32.u64 %0, t; }"
        : "=r"(a) : "l"(p));
    return a;
}

#define CP16(dst, src) \
    asm volatile("cp.async.cg.shared.global [%0], [%1], 16;" :: "r"(dst), "l"(src))
#define CP_COMMIT() asm volatile("cp.async.commit_group;" ::: "memory")
#define CP_WAIT2()  asm volatile("cp.async.wait_group 2;" ::: "memory")

__device__ __forceinline__ void mma16(float* d, const uint32_t* a, const uint32_t* b) {
    asm volatile(
        "mma.sync.aligned.m16n8k16.row.col.f32.f16.f16.f32 "
        "{%0,%1,%2,%3},{%4,%5,%6,%7},{%8,%9},{%0,%1,%2,%3};"
        : "+f"(d[0]), "+f"(d[1]), "+f"(d[2]), "+f"(d[3])
        : "r"(a[0]), "r"(a[1]), "r"(a[2]), "r"(a[3]), "r"(b[0]), "r"(b[1]));
}

__device__ __forceinline__ void ldsm4(uint32_t* r, uint32_t addr) {
    asm volatile(
        "ldmatrix.sync.aligned.m8n8.x4.shared.b16 {%0,%1,%2,%3}, [%4];"
        : "=r"(r[0]), "=r"(r[1]), "=r"(r[2]), "=r"(r[3]) : "r"(addr));
}

// ---------------------------------------------------------------------------
// Per-stage compute: 2 k16 steps, warp tile 64x32, single-pass fp16.
// ---------------------------------------------------------------------------
__device__ __forceinline__ void compute_tile(
    uint32_t buf, float (&acc)[4][4][4], uint32_t aBase, uint32_t bBase)
{
#pragma unroll
    for (int ks = 0; ks < 2; ks++) {
        const uint32_t kb = ks * 32;
        uint32_t bh[2][4];
#pragma unroll
        for (int ntp = 0; ntp < 2; ntp++)
            ldsm4(bh[ntp], buf + PL + bBase + ntp * 16 * ROWB + kb);
#pragma unroll
        for (int mt = 0; mt < 4; mt++) {
            uint32_t af[4];
            ldsm4(af, buf + aBase + mt * 16 * ROWB + kb);
#pragma unroll
            for (int nt = 0; nt < 4; nt++) {
                const int ntp = nt >> 1, s = nt & 1;
                uint32_t b0[2] = {bh[ntp][s], bh[ntp][s + 2]};
                mma16(acc[mt][nt], af, b0);
            }
        }
    }
}

// ---------------------------------------------------------------------------
// NT GEMM on fp16 planes: C[m,n] = sum_k A[m,k]*B[n,k]
// MODE 0: projection  -> half plane + bias
// MODE 2: scores      -> fp32, scale + causal mask (skip masked tiles)
// MODE 3: PV/out      -> fp32 plain, Kend = m0+BM
// ---------------------------------------------------------------------------
template <int MODE>
__global__ __launch_bounds__(256, 2) void gemm_h(
    const __half* __restrict__ A, const __half* __restrict__ Bh,
    const float* __restrict__ bias, void* __restrict__ C0,
    int K, int lda, int ldb, int ldc,
    long sAz, long sBz, long sCz, float scale)
{
    const int m0 = blockIdx.y * BM;
    const int n0 = blockIdx.x * BN;
    if (MODE == 2 && n0 > m0) return;  // fully masked tile

    const int z = blockIdx.z;
    A  += (size_t)z * sAz;
    Bh += (size_t)z * sBz;

    extern __shared__ char smx[];
    const uint32_t smb = smem_u32(smx);

    const int tid  = threadIdx.x;
    const int lane = tid & 31;
    const int wid  = tid >> 5;
    const int wm   = wid >> 2;   // 0..1 (64 rows)
    const int wn   = wid & 3;    // 0..3 (32 cols)
    const int g    = lane >> 2;
    const int tg   = lane & 3;

    // ldmatrix lane addressing
    const uint32_t lq = lane & 15, lh = lane >> 4;
    const uint32_t aBase = (wm * 64 + lq) * ROWB + lh * 16;
    const uint32_t bBase = (wn * 32 + lq) * ROWB + lh * 16;

    const int Kend = (MODE == 3) ? (m0 + BM) : K;
    const int KT   = Kend / BK;

    // cp.async mapping: rows lr4 and lr4+64, 16B segment c16 of the 64B row
    const int lr4 = tid >> 2;
    const int c16 = tid & 3;
    const __half* pA  = A  + (size_t)(m0 + lr4) * lda + c16 * 8;
    const __half* pBh = Bh + (size_t)(n0 + lr4) * ldb + c16 * 8;
    const size_t a64 = (size_t)64 * lda, b64 = (size_t)64 * ldb;
    const uint32_t dst0 = smb + lr4 * ROWB + c16 * 16;

    float acc[4][4][4];
#pragma unroll
    for (int i = 0; i < 4; i++)
#pragma unroll
        for (int j = 0; j < 4; j++)
#pragma unroll
            for (int e = 0; e < 4; e++) acc[i][j][e] = 0.f;

#define ISSUE(kt)                                                          \
    do {                                                                   \
        const uint32_t d = dst0 + ((kt) % NST) * STG;                      \
        const int koff = (kt) * BK;                                        \
        CP16(d,                  pA  + koff);                              \
        CP16(d + 64 * ROWB,      pA  + koff + a64);                        \
        CP16(d + PL,             pBh + koff);                              \
        CP16(d + PL + 64 * ROWB, pBh + koff + b64);                        \
        CP_COMMIT();                                                       \
    } while (0)

    ISSUE(0);
    ISSUE(1);
    ISSUE(2);

    for (int kt = 0; kt < KT; kt++) {
        CP_WAIT2();          // stage kt resident (≤2 groups outstanding)
        __syncthreads();     // all warps done with the buffer being rewritten
        if (kt + 3 < KT) ISSUE(kt + 3);
        compute_tile(smb + (kt % NST) * STG, acc, aBase, bBase);
    }
#undef ISSUE

    // epilogue
#pragma unroll
    for (int mt = 0; mt < 4; mt++)
#pragma unroll
        for (int nt = 0; nt < 4; nt++) {
            const int row = m0 + wm * 64 + mt * 16 + g;
            const int col = n0 + wn * 32 + nt * 8 + tg * 2;
            float* c = acc[mt][nt];
            if (MODE == 0) {
                __half* Ch = (__half*)C0;
                const float2 b2 = *(const float2*)(bias + col);
                __half2 h0 = __floats2half2_rn(c[0] + b2.x, c[1] + b2.y);
                __half2 h1 = __floats2half2_rn(c[2] + b2.x, c[3] + b2.y);
                *(__half2*)(Ch + (size_t)row * ldc + col)       = h0;
                *(__half2*)(Ch + (size_t)(row + 8) * ldc + col) = h1;
            } else if (MODE == 2) {
                float* C = (float*)C0 + (size_t)z * sCz;
                float2 v0, v1;
                v0.x = (col     <= row    ) ? c[0] * scale : -1e9f;
                v0.y = (col + 1 <= row    ) ? c[1] * scale : -1e9f;
                v1.x = (col     <= row + 8) ? c[2] * scale : -1e9f;
                v1.y = (col + 1 <= row + 8) ? c[3] * scale : -1e9f;
                *(float2*)(C + (size_t)row * ldc + col)       = v0;
                *(float2*)(C + (size_t)(row + 8) * ldc + col) = v1;
            } else {
                float* C = (float*)C0 + (size_t)z * sCz;
                *(float2*)(C + (size_t)row * ldc + col)       = make_float2(c[0], c[1]);
                *(float2*)(C + (size_t)(row + 8) * ldc + col) = make_float2(c[2], c[3]);
            }
        }
}

// ---------------------------------------------------------------------------
// fp32 -> fp16 conversion
// ---------------------------------------------------------------------------
__global__ __launch_bounds__(256) void cvt_h(
    const float* __restrict__ in, __half* __restrict__ out)
{
    const size_t i = ((size_t)blockIdx.x * 256 + threadIdx.x) * 4;
    float4 v = *(const float4*)(in + i);
    __half2 a = __floats2half2_rn(v.x, v.y);
    __half2 b = __floats2half2_rn(v.z, v.w);
    *(__half2*)(out + i)     = a;
    *(__half2*)(out + i + 2) = b;
}

// ---------------------------------------------------------------------------
// fp16 transpose: in [M_][H_] -> out [H_][M_]
// ---------------------------------------------------------------------------
__global__ __launch_bounds__(256) void transpose_h(
    const __half* __restrict__ in, __half* __restrict__ out)
{
    __shared__ __half t[32][34];
    const int x0 = blockIdx.x * 32;
    const int y0 = blockIdx.y * 32;
    const int tx = threadIdx.x & 31;
    const int ty = threadIdx.x >> 5;
#pragma unroll
    for (int j = 0; j < 32; j += 8)
        t[ty + j][tx] = in[(size_t)(y0 + ty + j) * H_ + x0 + tx];
    __syncthreads();
#pragma unroll
    for (int j = 0; j < 32; j += 8)
        out[(size_t)(x0 + ty + j) * M_ + y0 + tx] = t[tx][ty + j];
}

// ---------------------------------------------------------------------------
// Row softmax: read fp32 scores, write fp16 probabilities (causal prefix).
// ---------------------------------------------------------------------------
__global__ __launch_bounds__(256) void softmax_rows(
    const float* __restrict__ P, __half* __restrict__ Ph)
{
    const int r = blockIdx.x;
    const int m = r & (S_ - 1);
    const float* row = P + (size_t)r * S_;
    __half* orow = Ph + (size_t)r * S_;
    const int KB = ((m >> 7) + 1) << 7;

    __shared__ float buf[S_];
    __shared__ float red[8];
    const int tid = threadIdx.x;

    float mx = -3.4e38f;
    for (int i = tid; i < KB; i += 256) {
        float v = row[i];
        buf[i] = v;
        mx = fmaxf(mx, v);
    }
#pragma unroll
    for (int o = 16; o; o >>= 1) mx = fmaxf(mx, __shfl_xor_sync(0xffffffffu, mx, o));
    if ((tid & 31) == 0) red[tid >> 5] = mx;
    __syncthreads();
    if (tid == 0) {
        float t = red[0];
#pragma unroll
        for (int i = 1; i < 8; i++) t = fmaxf(t, red[i]);
        red[0] = t;
    }
    __syncthreads();
    mx = red[0];
    __syncthreads();

    float sm = 0.f;
    for (int i = tid; i < KB; i += 256) {
        float e = expf(buf[i] - mx);
        buf[i] = e;
        sm += e;
    }
#pragma unroll
    for (int o = 16; o; o >>= 1) sm += __shfl_xor_sync(0xffffffffu, sm, o);
    __syncthreads();
    if ((tid & 31) == 0) red[tid >> 5] = sm;
    __syncthreads();
    if (tid == 0) {
        float t = 0.f;
#pragma unroll
        for (int i = 0; i < 8; i++) t += red[i];
        red[0] = t;
    }
    __syncthreads();
    const float inv = 1.f / red[0];

    for (int i = tid; i < KB; i += 256)
        orow[i] = __float2half_rn(buf[i] * inv);
}

// ---------------------------------------------------------------------------
// Launch pipeline (graph-capturable)
// ---------------------------------------------------------------------------
extern "C" void kernel_launch(void* const* d_in, const int* in_sizes, int n_in,
                              void* d_out, int out_size)
{
    (void)in_sizes; (void)n_in; (void)out_size;
    const float* x  = (const float*)d_in[0];
    const float* Wq = (const float*)d_in[1];
    const float* bq = (const float*)d_in[2];
    const float* Wk = (const float*)d_in[3];
    const float* bk = (const float*)d_in[4];
    const float* Wv = (const float*)d_in[5];
    const float* bv = (const float*)d_in[6];
    float* out = (float*)d_out;

    __half *xh, *qh, *kh, *vh, *vth, *ph;
    __half (*wh)[(size_t)H_ * D_];
    float* p;
    cudaGetSymbolAddress((void**)&xh,  g_xh);
    cudaGetSymbolAddress((void**)&wh,  g_wh);
    cudaGetSymbolAddress((void**)&qh,  g_qh);
    cudaGetSymbolAddress((void**)&kh,  g_kh);
    cudaGetSymbolAddress((void**)&vh,  g_vh);
    cudaGetSymbolAddress((void**)&vth, g_vth);
    cudaGetSymbolAddress((void**)&p,   g_p);
    cudaGetSymbolAddress((void**)&ph,  g_ph);

    cudaFuncSetAttribute(gemm_h<0>, cudaFuncAttributeMaxDynamicSharedMemorySize, SMEM_BYTES);
    cudaFuncSetAttribute(gemm_h<2>, cudaFuncAttributeMaxDynamicSharedMemorySize, SMEM_BYTES);
    cudaFuncSetAttribute(gemm_h<3>, cudaFuncAttributeMaxDynamicSharedMemorySize, SMEM_BYTES);

    const dim3 blk(256);

    // 0) convert operands to fp16
    cvt_h<<<M_ * D_ / 1024, blk>>>(x, xh);
    cvt_h<<<H_ * D_ / 1024, blk>>>(Wq, wh[0]);
    cvt_h<<<H_ * D_ / 1024, blk>>>(Wk, wh[1]);
    cvt_h<<<H_ * D_ / 1024, blk>>>(Wv, wh[2]);

    // 1) QKV projections
    const dim3 gq(H_ / BN, M_ / BM, 1);
    gemm_h<0><<<gq, blk, SMEM_BYTES>>>(xh, wh[0], bq, qh, D_, D_, D_, H_, 0, 0, 0, 1.f);
    gemm_h<0><<<gq, blk, SMEM_BYTES>>>(xh, wh[1], bk, kh, D_, D_, D_, H_, 0, 0, 0, 1.f);
    gemm_h<0><<<gq, blk, SMEM_BYTES>>>(xh, wh[2], bv, vh, D_, D_, D_, H_, 0, 0, 0, 1.f);

    // 1b) V^T for the PV GEMM
    const dim3 gt(H_ / 32, M_ / 32);
    transpose_h<<<gt, blk>>>(vh, vth);

    // 2) Scores: per batch, Q @ K^T / 32, causal
    const dim3 gs(S_ / BN, S_ / BM, B_);
    gemm_h<2><<<gs, blk, SMEM_BYTES>>>(qh, kh, nullptr, p,
                                       H_, H_, H_, S_,
                                       (long)S_ * H_, (long)S_ * H_, (long)S_ * S_,
                                       0.03125f);

    // 3) Row softmax -> fp16 P
    softmax_rows<<<M_, blk>>>(p, ph);

    // 4) O = P @ V (B = V^T, causal k-limit)
    const dim3 gp(H_ / BN, S_ / BM, B_);
    gemm_h<3><<<gp, blk, SMEM_BYTES>>>(ph, vth, nullptr, out,
                                       S_, S_, M_, H_,
                                       (long)S_ * S_, (long)S_, (long)S_ * H_, 1.f);
}

// round 9
// speedup vs baseline: 1.8091x; 1.0272x over previous
#include <cuda_runtime.h>
#include <cuda_fp16.h>
#include <cstdint>
#include <math.h>

static constexpr int B_ = 8, S_ = 2048, D_ = 1024, H_ = 1024;
static constexpr int M_ = B_ * S_;  // 16384

// Tiling: 128x128 CTA tile, BK=32. fp16 planes in SMEM: A_h, B_h.
static constexpr int BM = 128, BN = 128, BK = 32;
static constexpr int ROWB = 80;                    // 64 data bytes + 16 pad
static constexpr int PL = BM * ROWB;               // 10240 per plane
static constexpr int STG = 2 * PL;                 // 20480 per stage
static constexpr int NST = 4;
static constexpr int SMEM_BYTES = NST * STG;       // 81920

static constexpr float SHIFT = 3.0f;               // exp(s - SHIFT), cancels in norm
static constexpr float LOG2E = 1.4426950408889634f;

// Device scratch (allocation-free rule: __device__ globals)
__device__ __half g_xh[(size_t)M_ * D_];
__device__ __half g_wh[3][(size_t)H_ * D_];
__device__ __half g_qh[(size_t)M_ * H_];
__device__ __half g_kh[(size_t)M_ * H_];
__device__ __half g_vh[(size_t)M_ * H_];
__device__ __half g_vth[(size_t)M_ * H_];
__device__ __half g_ph[(size_t)B_ * S_ * S_];
__device__ float  g_rinv[M_];

// ---------------------------------------------------------------------------
// helpers
// ---------------------------------------------------------------------------
__device__ __forceinline__ uint32_t smem_u32(const void* p) {
    uint32_t a;
    asm("{ .reg .u64 t; cvta.to.shared.u64 t, %1; cvt.u32.u64 %0, t; }"
        : "=r"(a) : "l"(p));
    return a;
}

#define CP16(dst, src) \
    asm volatile("cp.async.cg.shared.global [%0], [%1], 16;" :: "r"(dst), "l"(src))
#define CP_COMMIT() asm volatile("cp.async.commit_group;" ::: "memory")
#define CP_WAIT2()  asm volatile("cp.async.wait_group 2;" ::: "memory")

__device__ __forceinline__ void mma16(float* d, const uint32_t* a, const uint32_t* b) {
    asm volatile(
        "mma.sync.aligned.m16n8k16.row.col.f32.f16.f16.f32 "
        "{%0,%1,%2,%3},{%4,%5,%6,%7},{%8,%9},{%0,%1,%2,%3};"
        : "+f"(d[0]), "+f"(d[1]), "+f"(d[2]), "+f"(d[3])
        : "r"(a[0]), "r"(a[1]), "r"(a[2]), "r"(a[3]), "r"(b[0]), "r"(b[1]));
}

__device__ __forceinline__ void ldsm4(uint32_t* r, uint32_t addr) {
    asm volatile(
        "ldmatrix.sync.aligned.m8n8.x4.shared.b16 {%0,%1,%2,%3}, [%4];"
        : "=r"(r[0]), "=r"(r[1]), "=r"(r[2]), "=r"(r[3]) : "r"(addr));
}

// ---------------------------------------------------------------------------
// Per-stage compute: 2 k16 steps, warp tile 64x32, single-pass fp16.
// ---------------------------------------------------------------------------
__device__ __forceinline__ void compute_tile(
    uint32_t buf, float (&acc)[4][4][4], uint32_t aBase, uint32_t bBase)
{
#pragma unroll
    for (int ks = 0; ks < 2; ks++) {
        const uint32_t kb = ks * 32;
        uint32_t bh[2][4];
#pragma unroll
        for (int ntp = 0; ntp < 2; ntp++)
            ldsm4(bh[ntp], buf + PL + bBase + ntp * 16 * ROWB + kb);
#pragma unroll
        for (int mt = 0; mt < 4; mt++) {
            uint32_t af[4];
            ldsm4(af, buf + aBase + mt * 16 * ROWB + kb);
#pragma unroll
            for (int nt = 0; nt < 4; nt++) {
                const int ntp = nt >> 1, s = nt & 1;
                uint32_t b0[2] = {bh[ntp][s], bh[ntp][s + 2]};
                mma16(acc[mt][nt], af, b0);
            }
        }
    }
}

// ---------------------------------------------------------------------------
// NT GEMM on fp16 planes: C[m,n] = sum_k A[m,k]*B[n,k]
// MODE 0: projection  -> half plane + bias
// MODE 2: scores      -> fp16 exp(s*scale - SHIFT), causal (0 above diag)
// MODE 3: PV          -> fp32 * rinv[row], Kend = m0+BM
// ---------------------------------------------------------------------------
template <int MODE>
__global__ __launch_bounds__(256, 2) void gemm_h(
    const __half* __restrict__ A, const __half* __restrict__ Bh,
    const float* __restrict__ bias, void* __restrict__ C0,
    const float* __restrict__ rinv,
    int K, int lda, int ldb, int ldc,
    long sAz, long sBz, long sCz, float scale)
{
    const int m0 = blockIdx.y * BM;
    const int n0 = blockIdx.x * BN;
    if (MODE == 2 && n0 > m0) return;  // fully masked tile

    const int z = blockIdx.z;
    A  += (size_t)z * sAz;
    Bh += (size_t)z * sBz;

    extern __shared__ char smx[];
    const uint32_t smb = smem_u32(smx);

    const int tid  = threadIdx.x;
    const int lane = tid & 31;
    const int wid  = tid >> 5;
    const int wm   = wid >> 2;   // 0..1 (64 rows)
    const int wn   = wid & 3;    // 0..3 (32 cols)
    const int g    = lane >> 2;
    const int tg   = lane & 3;

    // ldmatrix lane addressing
    const uint32_t lq = lane & 15, lh = lane >> 4;
    const uint32_t aBase = (wm * 64 + lq) * ROWB + lh * 16;
    const uint32_t bBase = (wn * 32 + lq) * ROWB + lh * 16;

    const int Kend = (MODE == 3) ? (m0 + BM) : K;
    const int KT   = Kend / BK;

    // cp.async mapping: rows lr4 and lr4+64, 16B segment c16 of the 64B row
    const int lr4 = tid >> 2;
    const int c16 = tid & 3;
    const __half* pA  = A  + (size_t)(m0 + lr4) * lda + c16 * 8;
    const __half* pBh = Bh + (size_t)(n0 + lr4) * ldb + c16 * 8;
    const size_t a64 = (size_t)64 * lda, b64 = (size_t)64 * ldb;
    const uint32_t dst0 = smb + lr4 * ROWB + c16 * 16;

    float acc[4][4][4];
#pragma unroll
    for (int i = 0; i < 4; i++)
#pragma unroll
        for (int j = 0; j < 4; j++)
#pragma unroll
            for (int e = 0; e < 4; e++) acc[i][j][e] = 0.f;

#define ISSUE(kt)                                                          \
    do {                                                                   \
        const uint32_t d = dst0 + ((kt) % NST) * STG;                      \
        const int koff = (kt) * BK;                                        \
        CP16(d,                  pA  + koff);                              \
        CP16(d + 64 * ROWB,      pA  + koff + a64);                        \
        CP16(d + PL,             pBh + koff);                              \
        CP16(d + PL + 64 * ROWB, pBh + koff + b64);                        \
        CP_COMMIT();                                                       \
    } while (0)

    ISSUE(0);
    ISSUE(1);
    ISSUE(2);

    for (int kt = 0; kt < KT; kt++) {
        CP_WAIT2();          // stage kt resident (<=2 groups outstanding)
        __syncthreads();     // all warps done with the buffer being rewritten
        if (kt + 3 < KT) ISSUE(kt + 3);
        compute_tile(smb + (kt % NST) * STG, acc, aBase, bBase);
    }
#undef ISSUE

    // epilogue
#pragma unroll
    for (int mt = 0; mt < 4; mt++)
#pragma unroll
        for (int nt = 0; nt < 4; nt++) {
            const int row = m0 + wm * 64 + mt * 16 + g;
            const int col = n0 + wn * 32 + nt * 8 + tg * 2;
            float* c = acc[mt][nt];
            if (MODE == 0) {
                __half* Ch = (__half*)C0;
                const float2 b2 = *(const float2*)(bias + col);
                __half2 h0 = __floats2half2_rn(c[0] + b2.x, c[1] + b2.y);
                __half2 h1 = __floats2half2_rn(c[2] + b2.x, c[3] + b2.y);
                *(__half2*)(Ch + (size_t)row * ldc + col)       = h0;
                *(__half2*)(Ch + (size_t)(row + 8) * ldc + col) = h1;
            } else if (MODE == 2) {
                __half* Ph = (__half*)C0 + (size_t)z * sCz;
                float e0 = (col     <= row    ) ? exp2f((c[0] * scale - SHIFT) * LOG2E) : 0.f;
                float e1 = (col + 1 <= row    ) ? exp2f((c[1] * scale - SHIFT) * LOG2E) : 0.f;
                float e2 = (col     <= row + 8) ? exp2f((c[2] * scale - SHIFT) * LOG2E) : 0.f;
                float e3 = (col + 1 <= row + 8) ? exp2f((c[3] * scale - SHIFT) * LOG2E) : 0.f;
                *(__half2*)(Ph + (size_t)row * ldc + col)       = __floats2half2_rn(e0, e1);
                *(__half2*)(Ph + (size_t)(row + 8) * ldc + col) = __floats2half2_rn(e2, e3);
            } else {
                float* C = (float*)C0 + (size_t)z * sCz;
                const float r0 = rinv[z * S_ + row];
                const float r1 = rinv[z * S_ + row + 8];
                *(float2*)(C + (size_t)row * ldc + col) =
                    make_float2(c[0] * r0, c[1] * r0);
                *(float2*)(C + (size_t)(row + 8) * ldc + col) =
                    make_float2(c[2] * r1, c[3] * r1);
            }
        }
}

// ---------------------------------------------------------------------------
// fp32 -> fp16 conversion
// ---------------------------------------------------------------------------
__global__ __launch_bounds__(256) void cvt_h(
    const float* __restrict__ in, __half* __restrict__ out)
{
    const size_t i = ((size_t)blockIdx.x * 256 + threadIdx.x) * 4;
    float4 v = *(const float4*)(in + i);
    __half2 a = __floats2half2_rn(v.x, v.y);
    __half2 b = __floats2half2_rn(v.z, v.w);
    *(__half2*)(out + i)     = a;
    *(__half2*)(out + i + 2) = b;
}

// ---------------------------------------------------------------------------
// fp16 transpose: in [M_][H_] -> out [H_][M_]
// ---------------------------------------------------------------------------
__global__ __launch_bounds__(256) void transpose_h(
    const __half* __restrict__ in, __half* __restrict__ out)
{
    __shared__ __half t[32][34];
    const int x0 = blockIdx.x * 32;
    const int y0 = blockIdx.y * 32;
    const int tx = threadIdx.x & 31;
    const int ty = threadIdx.x >> 5;
#pragma unroll
    for (int j = 0; j < 32; j += 8)
        t[ty + j][tx] = in[(size_t)(y0 + ty + j) * H_ + x0 + tx];
    __syncthreads();
#pragma unroll
    for (int j = 0; j < 32; j += 8)
        out[(size_t)(x0 + ty + j) * M_ + y0 + tx] = t[tx][ty + j];
}

// ---------------------------------------------------------------------------
// Row sum of p~ over the causal prefix -> rinv = 1/sum (deterministic).
// ---------------------------------------------------------------------------
__global__ __launch_bounds__(256) void rowsum_k(
    const __half* __restrict__ Ph, float* __restrict__ rinv)
{
    const int r = blockIdx.x;
    const int m = r & (S_ - 1);
    const __half* row = Ph + (size_t)r * S_;
    const int KB = ((m >> 7) + 1) << 7;  // round_up(m+1,128)

    __shared__ float red[8];
    const int tid = threadIdx.x;

    float sm = 0.f;
    for (int i = tid * 2; i < KB; i += 512) {
        __half2 v = *(const __half2*)(row + i);
        float2 f = __half22float2(v);
        sm += f.x + f.y;
    }
#pragma unroll
    for (int o = 16; o; o >>= 1) sm += __shfl_xor_sync(0xffffffffu, sm, o);
    if ((tid & 31) == 0) red[tid >> 5] = sm;
    __syncthreads();
    if (tid == 0) {
        float t = 0.f;
#pragma unroll
        for (int i = 0; i < 8; i++) t += red[i];
        rinv[r] = 1.f / t;
    }
}

// ---------------------------------------------------------------------------
// Launch pipeline (graph-capturable)
// ---------------------------------------------------------------------------
extern "C" void kernel_launch(void* const* d_in, const int* in_sizes, int n_in,
                              void* d_out, int out_size)
{
    (void)in_sizes; (void)n_in; (void)out_size;
    const float* x  = (const float*)d_in[0];
    const float* Wq = (const float*)d_in[1];
    const float* bq = (const float*)d_in[2];
    const float* Wk = (const float*)d_in[3];
    const float* bk = (const float*)d_in[4];
    const float* Wv = (const float*)d_in[5];
    const float* bv = (const float*)d_in[6];
    float* out = (float*)d_out;

    __half *xh, *qh, *kh, *vh, *vth, *ph;
    __half (*wh)[(size_t)H_ * D_];
    float* rinv;
    cudaGetSymbolAddress((void**)&xh,   g_xh);
    cudaGetSymbolAddress((void**)&wh,   g_wh);
    cudaGetSymbolAddress((void**)&qh,   g_qh);
    cudaGetSymbolAddress((void**)&kh,   g_kh);
    cudaGetSymbolAddress((void**)&vh,   g_vh);
    cudaGetSymbolAddress((void**)&vth,  g_vth);
    cudaGetSymbolAddress((void**)&ph,   g_ph);
    cudaGetSymbolAddress((void**)&rinv, g_rinv);

    cudaFuncSetAttribute(gemm_h<0>, cudaFuncAttributeMaxDynamicSharedMemorySize, SMEM_BYTES);
    cudaFuncSetAttribute(gemm_h<2>, cudaFuncAttributeMaxDynamicSharedMemorySize, SMEM_BYTES);
    cudaFuncSetAttribute(gemm_h<3>, cudaFuncAttributeMaxDynamicSharedMemorySize, SMEM_BYTES);

    const dim3 blk(256);

    // 0) convert operands to fp16
    cvt_h<<<M_ * D_ / 1024, blk>>>(x, xh);
    cvt_h<<<H_ * D_ / 1024, blk>>>(Wq, wh[0]);
    cvt_h<<<H_ * D_ / 1024, blk>>>(Wk, wh[1]);
    cvt_h<<<H_ * D_ / 1024, blk>>>(Wv, wh[2]);

    // 1) QKV projections
    const dim3 gq(H_ / BN, M_ / BM, 1);
    gemm_h<0><<<gq, blk, SMEM_BYTES>>>(xh, wh[0], bq, qh, nullptr,
                                       D_, D_, D_, H_, 0, 0, 0, 1.f);
    gemm_h<0><<<gq, blk, SMEM_BYTES>>>(xh, wh[1], bk, kh, nullptr,
                                       D_, D_, D_, H_, 0, 0, 0, 1.f);
    gemm_h<0><<<gq, blk, SMEM_BYTES>>>(xh, wh[2], bv, vh, nullptr,
                                       D_, D_, D_, H_, 0, 0, 0, 1.f);

    // 1b) V^T for the PV GEMM
    const dim3 gt(H_ / 32, M_ / 32);
    transpose_h<<<gt, blk>>>(vh, vth);

    // 2) Scores -> p~ = exp(s/32 - SHIFT), fp16, causal
    const dim3 gs(S_ / BN, S_ / BM, B_);
    gemm_h<2><<<gs, blk, SMEM_BYTES>>>(qh, kh, nullptr, ph, nullptr,
                                       H_, H_, H_, S_,
                                       (long)S_ * H_, (long)S_ * H_, (long)S_ * S_,
                                       0.03125f);

    // 3) rinv[r] = 1 / rowsum(p~)
    rowsum_k<<<M_, blk>>>(ph, rinv);

    // 4) O = (p~ @ V) * rinv  (B = V^T, causal k-limit)
    const dim3 gp(H_ / BN, S_ / BM, B_);
    gemm_h<3><<<gp, blk, SMEM_BYTES>>>(ph, vth, nullptr, out, rinv,
                                       S_, S_, M_, H_,
                                       (long)S_ * S_, (long)S_, (long)S_ * H_, 1.f);
}

// round 10
// speedup vs baseline: 1.8629x; 1.0297x over previous
#include <cuda_runtime.h>
#include <cuda_fp16.h>
#include <cstdint>
#include <math.h>

static constexpr int B_ = 8, S_ = 2048, D_ = 1024, H_ = 1024;
static constexpr int M_ = B_ * S_;  // 16384

// Tiling: 128x128 CTA tile, BK=32. fp16 planes in SMEM: A_h, B_h.
static constexpr int BM = 128, BN = 128, BK = 32;
static constexpr int ROWB = 80;                    // 64 data bytes + 16 pad
static constexpr int PL = BM * ROWB;               // 10240 per plane
static constexpr int STG = 2 * PL;                 // 20480 per stage
static constexpr int NST = 4;
static constexpr int SMEM_BYTES = NST * STG;       // 81920

static constexpr float SHIFT = 3.0f;               // exp(s - SHIFT), cancels in norm
static constexpr float LOG2E = 1.4426950408889634f;

// Device scratch (allocation-free rule: __device__ globals)
__device__ __half g_xh[(size_t)M_ * D_];
__device__ __half g_wh[3][(size_t)H_ * D_];
__device__ __half g_qkv[3][(size_t)M_ * H_];       // q, k, v planes
__device__ __half g_vth[(size_t)M_ * H_];
__device__ __half g_ph[(size_t)B_ * S_ * S_];
__device__ float  g_rinv[M_];

// ---------------------------------------------------------------------------
// helpers
// ---------------------------------------------------------------------------
__device__ __forceinline__ uint32_t smem_u32(const void* p) {
    uint32_t a;
    asm("{ .reg .u64 t; cvta.to.shared.u64 t, %1; cvt.u32.u64 %0, t; }"
        : "=r"(a) : "l"(p));
    return a;
}

#define CP16(dst, src) \
    asm volatile("cp.async.cg.shared.global [%0], [%1], 16;" :: "r"(dst), "l"(src))
#define CP_COMMIT() asm volatile("cp.async.commit_group;" ::: "memory")
#define CP_WAIT2()  asm volatile("cp.async.wait_group 2;" ::: "memory")

__device__ __forceinline__ void mma16(float* d, const uint32_t* a, const uint32_t* b) {
    asm volatile(
        "mma.sync.aligned.m16n8k16.row.col.f32.f16.f16.f32 "
        "{%0,%1,%2,%3},{%4,%5,%6,%7},{%8,%9},{%0,%1,%2,%3};"
        : "+f"(d[0]), "+f"(d[1]), "+f"(d[2]), "+f"(d[3])
        : "r"(a[0]), "r"(a[1]), "r"(a[2]), "r"(a[3]), "r"(b[0]), "r"(b[1]));
}

__device__ __forceinline__ void ldsm4(uint32_t* r, uint32_t addr) {
    asm volatile(
        "ldmatrix.sync.aligned.m8n8.x4.shared.b16 {%0,%1,%2,%3}, [%4];"
        : "=r"(r[0]), "=r"(r[1]), "=r"(r[2]), "=r"(r[3]) : "r"(addr));
}

// ---------------------------------------------------------------------------
// Per-stage compute: 2 k16 steps, warp tile 64x32, single-pass fp16.
// ---------------------------------------------------------------------------
__device__ __forceinline__ void compute_tile(
    uint32_t buf, float (&acc)[4][4][4], uint32_t aBase, uint32_t bBase)
{
#pragma unroll
    for (int ks = 0; ks < 2; ks++) {
        const uint32_t kb = ks * 32;
        uint32_t bh[2][4];
#pragma unroll
        for (int ntp = 0; ntp < 2; ntp++)
            ldsm4(bh[ntp], buf + PL + bBase + ntp * 16 * ROWB + kb);
#pragma unroll
        for (int mt = 0; mt < 4; mt++) {
            uint32_t af[4];
            ldsm4(af, buf + aBase + mt * 16 * ROWB + kb);
#pragma unroll
            for (int nt = 0; nt < 4; nt++) {
                const int ntp = nt >> 1, s = nt & 1;
                uint32_t b0[2] = {bh[ntp][s], bh[ntp][s + 2]};
                mma16(acc[mt][nt], af, b0);
            }
        }
    }
}

// ---------------------------------------------------------------------------
// NT GEMM on fp16 planes: C[m,n] = sum_k A[m,k]*B[n,k]
// MODE 0: fused QKV   -> z selects W plane / bias / output plane
// MODE 2: scores      -> triangular-packed grid; fp16 exp(s*scale - SHIFT)
// MODE 3: PV          -> fp32 * rinv[row], Kend = m0+BM, largest-K-first order
// ---------------------------------------------------------------------------
template <int MODE>
__global__ __launch_bounds__(256, 2) void gemm_h(
    const __half* __restrict__ A, const __half* __restrict__ Bh,
    const float* __restrict__ bias0, const float* __restrict__ bias1,
    const float* __restrict__ bias2, void* __restrict__ C0,
    const float* __restrict__ rinv,
    int K, int lda, int ldb, int ldc,
    long sAz, long sBz, long sCz, float scale)
{
    int m0, n0;
    if (MODE == 2) {
        // triangular decode: blockIdx.x in [0,136) -> (mt, nt), nt <= mt
        const int t = blockIdx.x;
        int mt = (int)((__fsqrt_rn(8.f * t + 1.f) - 1.f) * 0.5f);
        while ((mt + 1) * (mt + 2) / 2 <= t) mt++;
        while (mt * (mt + 1) / 2 > t) mt--;
        m0 = mt * BM;
        n0 = (t - mt * (mt + 1) / 2) * BN;
    } else if (MODE == 3) {
        m0 = ((int)gridDim.y - 1 - (int)blockIdx.y) * BM;  // largest K first
        n0 = blockIdx.x * BN;
    } else {
        m0 = blockIdx.y * BM;
        n0 = blockIdx.x * BN;
    }

    const int z = blockIdx.z;
    A  += (size_t)z * sAz;
    Bh += (size_t)z * sBz;

    extern __shared__ char smx[];
    const uint32_t smb = smem_u32(smx);

    const int tid  = threadIdx.x;
    const int lane = tid & 31;
    const int wid  = tid >> 5;
    const int wm   = wid >> 2;   // 0..1 (64 rows)
    const int wn   = wid & 3;    // 0..3 (32 cols)
    const int g    = lane >> 2;
    const int tg   = lane & 3;

    // ldmatrix lane addressing
    const uint32_t lq = lane & 15, lh = lane >> 4;
    const uint32_t aBase = (wm * 64 + lq) * ROWB + lh * 16;
    const uint32_t bBase = (wn * 32 + lq) * ROWB + lh * 16;

    const int Kend = (MODE == 3) ? (m0 + BM) : K;
    const int KT   = Kend / BK;

    // cp.async mapping: rows lr4 and lr4+64, 16B segment c16 of the 64B row
    const int lr4 = tid >> 2;
    const int c16 = tid & 3;
    const __half* pA  = A  + (size_t)(m0 + lr4) * lda + c16 * 8;
    const __half* pBh = Bh + (size_t)(n0 + lr4) * ldb + c16 * 8;
    const size_t a64 = (size_t)64 * lda, b64 = (size_t)64 * ldb;
    const uint32_t dst0 = smb + lr4 * ROWB + c16 * 16;

    float acc[4][4][4];
#pragma unroll
    for (int i = 0; i < 4; i++)
#pragma unroll
        for (int j = 0; j < 4; j++)
#pragma unroll
            for (int e = 0; e < 4; e++) acc[i][j][e] = 0.f;

#define ISSUE(kt)                                                          \
    do {                                                                   \
        const uint32_t d = dst0 + ((kt) % NST) * STG;                      \
        const int koff = (kt) * BK;                                        \
        CP16(d,                  pA  + koff);                              \
        CP16(d + 64 * ROWB,      pA  + koff + a64);                        \
        CP16(d + PL,             pBh + koff);                              \
        CP16(d + PL + 64 * ROWB, pBh + koff + b64);                        \
        CP_COMMIT();                                                       \
    } while (0)

    ISSUE(0);
    ISSUE(1);
    ISSUE(2);

    for (int kt = 0; kt < KT; kt++) {
        CP_WAIT2();          // stage kt resident (<=2 groups outstanding)
        __syncthreads();     // all warps done with the buffer being rewritten
        if (kt + 3 < KT) ISSUE(kt + 3);
        compute_tile(smb + (kt % NST) * STG, acc, aBase, bBase);
    }
#undef ISSUE

    // epilogue
#pragma unroll
    for (int mt = 0; mt < 4; mt++)
#pragma unroll
        for (int nt = 0; nt < 4; nt++) {
            const int row = m0 + wm * 64 + mt * 16 + g;
            const int col = n0 + wn * 32 + nt * 8 + tg * 2;
            float* c = acc[mt][nt];
            if (MODE == 0) {
                __half* Ch = (__half*)C0 + (size_t)z * sCz;
                const float* bias = (z == 0) ? bias0 : ((z == 1) ? bias1 : bias2);
                const float2 b2 = *(const float2*)(bias + col);
                __half2 h0 = __floats2half2_rn(c[0] + b2.x, c[1] + b2.y);
                __half2 h1 = __floats2half2_rn(c[2] + b2.x, c[3] + b2.y);
                *(__half2*)(Ch + (size_t)row * ldc + col)       = h0;
                *(__half2*)(Ch + (size_t)(row + 8) * ldc + col) = h1;
            } else if (MODE == 2) {
                __half* Ph = (__half*)C0 + (size_t)z * sCz;
                float e0 = (col     <= row    ) ? exp2f((c[0] * scale - SHIFT) * LOG2E) : 0.f;
                float e1 = (col + 1 <= row    ) ? exp2f((c[1] * scale - SHIFT) * LOG2E) : 0.f;
                float e2 = (col     <= row + 8) ? exp2f((c[2] * scale - SHIFT) * LOG2E) : 0.f;
                float e3 = (col + 1 <= row + 8) ? exp2f((c[3] * scale - SHIFT) * LOG2E) : 0.f;
                *(__half2*)(Ph + (size_t)row * ldc + col)       = __floats2half2_rn(e0, e1);
                *(__half2*)(Ph + (size_t)(row + 8) * ldc + col) = __floats2half2_rn(e2, e3);
            } else {
                float* C = (float*)C0 + (size_t)z * sCz;
                const float r0 = rinv[z * S_ + row];
                const float r1 = rinv[z * S_ + row + 8];
                *(float2*)(C + (size_t)row * ldc + col) =
                    make_float2(c[0] * r0, c[1] * r0);
                *(float2*)(C + (size_t)(row + 8) * ldc + col) =
                    make_float2(c[2] * r1, c[3] * r1);
            }
        }
}

// ---------------------------------------------------------------------------
// fp32 -> fp16 conversion (single src)
// ---------------------------------------------------------------------------
__global__ __launch_bounds__(256) void cvt_h(
    const float* __restrict__ in, __half* __restrict__ out)
{
    const size_t i = ((size_t)blockIdx.x * 256 + threadIdx.x) * 4;
    float4 v = *(const float4*)(in + i);
    *(__half2*)(out + i)     = __floats2half2_rn(v.x, v.y);
    *(__half2*)(out + i + 2) = __floats2half2_rn(v.z, v.w);
}

// fp32 -> fp16 conversion for the 3 weight matrices (z-indexed)
__global__ __launch_bounds__(256) void cvt_w(
    const float* __restrict__ w0, const float* __restrict__ w1,
    const float* __restrict__ w2, __half* __restrict__ out)
{
    const int z = blockIdx.y;
    const float* in = (z == 0) ? w0 : ((z == 1) ? w1 : w2);
    const size_t i = ((size_t)blockIdx.x * 256 + threadIdx.x) * 4;
    float4 v = *(const float4*)(in + i);
    __half* o = out + (size_t)z * H_ * D_;
    *(__half2*)(o + i)     = __floats2half2_rn(v.x, v.y);
    *(__half2*)(o + i + 2) = __floats2half2_rn(v.z, v.w);
}

// ---------------------------------------------------------------------------
// fp16 transpose: in [M_][H_] -> out [H_][M_]
// ---------------------------------------------------------------------------
__global__ __launch_bounds__(256) void transpose_h(
    const __half* __restrict__ in, __half* __restrict__ out)
{
    __shared__ __half t[32][34];
    const int x0 = blockIdx.x * 32;
    const int y0 = blockIdx.y * 32;
    const int tx = threadIdx.x & 31;
    const int ty = threadIdx.x >> 5;
#pragma unroll
    for (int j = 0; j < 32; j += 8)
        t[ty + j][tx] = in[(size_t)(y0 + ty + j) * H_ + x0 + tx];
    __syncthreads();
#pragma unroll
    for (int j = 0; j < 32; j += 8)
        out[(size_t)(x0 + ty + j) * M_ + y0 + tx] = t[tx][ty + j];
}

// ---------------------------------------------------------------------------
// Row sum of p~ over the causal prefix -> rinv = 1/sum (deterministic).
// ---------------------------------------------------------------------------
__global__ __launch_bounds__(256) void rowsum_k(
    const __half* __restrict__ Ph, float* __restrict__ rinv)
{
    const int r = blockIdx.x;
    const int m = r & (S_ - 1);
    const __half* row = Ph + (size_t)r * S_;
    const int KB = ((m >> 7) + 1) << 7;  // round_up(m+1,128)

    __shared__ float red[8];
    const int tid = threadIdx.x;

    float sm = 0.f;
    for (int i = tid * 2; i < KB; i += 512) {
        __half2 v = *(const __half2*)(row + i);
        float2 f = __half22float2(v);
        sm += f.x + f.y;
    }
#pragma unroll
    for (int o = 16; o; o >>= 1) sm += __shfl_xor_sync(0xffffffffu, sm, o);
    if ((tid & 31) == 0) red[tid >> 5] = sm;
    __syncthreads();
    if (tid == 0) {
        float t = 0.f;
#pragma unroll
        for (int i = 0; i < 8; i++) t += red[i];
        rinv[r] = 1.f / t;
    }
}

// ---------------------------------------------------------------------------
// Launch pipeline (graph-capturable)
// ---------------------------------------------------------------------------
extern "C" void kernel_launch(void* const* d_in, const int* in_sizes, int n_in,
                              void* d_out, int out_size)
{
    (void)in_sizes; (void)n_in; (void)out_size;
    const float* x  = (const float*)d_in[0];
    const float* Wq = (const float*)d_in[1];
    const float* bq = (const float*)d_in[2];
    const float* Wk = (const float*)d_in[3];
    const float* bk = (const float*)d_in[4];
    const float* Wv = (const float*)d_in[5];
    const float* bv = (const float*)d_in[6];
    float* out = (float*)d_out;

    __half *xh, *wh, *qkv, *vth, *ph;
    float* rinv;
    cudaGetSymbolAddress((void**)&xh,   g_xh);
    cudaGetSymbolAddress((void**)&wh,   g_wh);
    cudaGetSymbolAddress((void**)&qkv,  g_qkv);
    cudaGetSymbolAddress((void**)&vth,  g_vth);
    cudaGetSymbolAddress((void**)&ph,   g_ph);
    cudaGetSymbolAddress((void**)&rinv, g_rinv);

    const __half* qh = qkv;
    const __half* kh = qkv + (size_t)M_ * H_;
    const __half* vh = qkv + 2 * (size_t)M_ * H_;

    cudaFuncSetAttribute(gemm_h<0>, cudaFuncAttributeMaxDynamicSharedMemorySize, SMEM_BYTES);
    cudaFuncSetAttribute(gemm_h<2>, cudaFuncAttributeMaxDynamicSharedMemorySize, SMEM_BYTES);
    cudaFuncSetAttribute(gemm_h<3>, cudaFuncAttributeMaxDynamicSharedMemorySize, SMEM_BYTES);

    const dim3 blk(256);

    // 0) convert operands to fp16
    cvt_h<<<M_ * D_ / 1024, blk>>>(x, xh);
    cvt_w<<<dim3(H_ * D_ / 1024, 3), blk>>>(Wq, Wk, Wv, wh);

    // 1) fused QKV projection: one launch, z selects plane (wave packing)
    const dim3 gq(H_ / BN, M_ / BM, 3);  // 3072 CTAs
    gemm_h<0><<<gq, blk, SMEM_BYTES>>>(xh, wh, bq, bk, bv, qkv, nullptr,
                                       D_, D_, D_, H_,
                                       0, (long)H_ * D_, (long)M_ * H_, 1.f);

    // 1b) V^T for the PV GEMM
    transpose_h<<<dim3(H_ / 32, M_ / 32), blk>>>(vh, vth);

    // 2) Scores -> p~ = exp(s/32 - SHIFT), fp16, causal; packed triangular grid
    const dim3 gs(136, 1, B_);  // 1088 CTAs, all live
    gemm_h<2><<<gs, blk, SMEM_BYTES>>>(qh, kh, nullptr, nullptr, nullptr, ph, nullptr,
                                       H_, H_, H_, S_,
                                       (long)S_ * H_, (long)S_ * H_, (long)S_ * S_,
                                       0.03125f);

    // 3) rinv[r] = 1 / rowsum(p~)
    rowsum_k<<<M_, blk>>>(ph, rinv);

    // 4) O = (p~ @ V) * rinv  (B = V^T, causal k-limit, largest-K tiles first)
    const dim3 gp(H_ / BN, S_ / BM, B_);
    gemm_h<3><<<gp, blk, SMEM_BYTES>>>(ph, vth, nullptr, nullptr, nullptr, out, rinv,
                                       S_, S_, M_, H_,
                                       (long)S_ * S_, (long)S_, (long)S_ * H_, 1.f);
}